// round 2
// baseline (speedup 1.0000x reference)
#include <cuda_runtime.h>
#include <cuda_bf16.h>

// RAM multi-step transformer, split into 6 graph-captured kernels so every
// phase runs at high occupancy with its full set of random table lookups in
// flight. Bit state lives in tiny __device__ buffers, packed 32 bits/word.
//
// x:          (256, 1024) int32 bits
// conn_in:    (2048, 16)  int32 idx into [0,1024)
// conn_state: (1024, 16)  int32 idx into [0,3072)
// conn_out:   (512, 16)   int32 idx into [0,3072)
// mem_in:     (2048, 65536) f32 | mem_state: (1024, 65536) f32 | mem_out: (512, 65536) f32
// out:        (256, 512) f32

#define BATCH 256
#define IN_BITS 1024
#define N_IN 2048
#define N_ST 1024
#define N_OUT 512
#define TBL 65536
#define THREADS 256

// Packed bit state: 2048 in-bits = 64 words/batch; 1024 state bits = 32 words/batch.
__device__ unsigned g_in_words[BATCH * 64];
__device__ unsigned g_state_words[2 * BATCH * 32];

// Build 16-bit address from packed words in shared memory.
__device__ __forceinline__ unsigned gather16(const unsigned* __restrict__ sw,
                                             int4 c0, int4 c1, int4 c2, int4 c3) {
    unsigned a = 0;
    a |= ((sw[c0.x >> 5] >> (c0.x & 31)) & 1u) << 0;
    a |= ((sw[c0.y >> 5] >> (c0.y & 31)) & 1u) << 1;
    a |= ((sw[c0.z >> 5] >> (c0.z & 31)) & 1u) << 2;
    a |= ((sw[c0.w >> 5] >> (c0.w & 31)) & 1u) << 3;
    a |= ((sw[c1.x >> 5] >> (c1.x & 31)) & 1u) << 4;
    a |= ((sw[c1.y >> 5] >> (c1.y & 31)) & 1u) << 5;
    a |= ((sw[c1.z >> 5] >> (c1.z & 31)) & 1u) << 6;
    a |= ((sw[c1.w >> 5] >> (c1.w & 31)) & 1u) << 7;
    a |= ((sw[c2.x >> 5] >> (c2.x & 31)) & 1u) << 8;
    a |= ((sw[c2.y >> 5] >> (c2.y & 31)) & 1u) << 9;
    a |= ((sw[c2.z >> 5] >> (c2.z & 31)) & 1u) << 10;
    a |= ((sw[c2.w >> 5] >> (c2.w & 31)) & 1u) << 11;
    a |= ((sw[c3.x >> 5] >> (c3.x & 31)) & 1u) << 12;
    a |= ((sw[c3.y >> 5] >> (c3.y & 31)) & 1u) << 13;
    a |= ((sw[c3.z >> 5] >> (c3.z & 31)) & 1u) << 14;
    a |= ((sw[c3.w >> 5] >> (c3.w & 31)) & 1u) << 15;
    return a;
}

// ---- Input layer: grid 1024 = 256 batches x 4 chunks of 512 neurons (2/thread) ----
__global__ __launch_bounds__(THREADS)
void k_in(const int* __restrict__ x,
          const int4* __restrict__ conn_in,
          const float* __restrict__ mem_in) {
    __shared__ unsigned char sb[IN_BITS];
    __shared__ unsigned sw[32];   // 1024 bits packed -> conflict-free gather (1 word/bank)

    const int b = blockIdx.x >> 2;
    const int chunk = blockIdx.x & 3;
    const int tid = threadIdx.x;
    const int lane = tid & 31;

    // Coalesced load of x bits -> bytes -> packed words.
    const int4* xb = reinterpret_cast<const int4*>(x + b * IN_BITS);
    {
        int4 v = __ldg(xb + tid);
        sb[tid * 4 + 0] = (unsigned char)v.x;
        sb[tid * 4 + 1] = (unsigned char)v.y;
        sb[tid * 4 + 2] = (unsigned char)v.z;
        sb[tid * 4 + 3] = (unsigned char)v.w;
    }
    __syncthreads();
    if (tid < 32) {
        unsigned w = 0;
        #pragma unroll
        for (int j = 0; j < 32; j++) w |= ((unsigned)sb[tid * 32 + j]) << j;
        sw[tid] = w;
    }
    __syncthreads();

    #pragma unroll
    for (int r = 0; r < 2; r++) {
        int n = chunk * 512 + r * 256 + tid;           // warp-consecutive neurons
        const int4* c = conn_in + n * 4;
        int4 c0 = __ldg(c + 0), c1 = __ldg(c + 1), c2 = __ldg(c + 2), c3 = __ldg(c + 3);
        unsigned addr = gather16(sw, c0, c1, c2, c3);
        float v = __ldg(mem_in + (size_t)n * TBL + addr);
        unsigned word = __ballot_sync(0xFFFFFFFFu, v > 0.5f);
        if (lane == 0) g_in_words[b * 64 + (n >> 5)] = word;
    }
}

// ---- State iteration: grid 1024 = 256 batches x 4 chunks of 256 neurons ----
__global__ __launch_bounds__(THREADS)
void k_state(const int4* __restrict__ conn_state,
             const float* __restrict__ mem_state,
             int first, int rd, int wr) {
    __shared__ unsigned sw[96];   // [0,64) in bits, [64,96) state bits

    const int b = blockIdx.x >> 2;
    const int chunk = blockIdx.x & 3;
    const int tid = threadIdx.x;
    const int lane = tid & 31;

    if (tid < 64) {
        sw[tid] = g_in_words[b * 64 + tid];
    } else if (tid < 96) {
        sw[tid] = first ? 0u : g_state_words[rd * BATCH * 32 + b * 32 + (tid - 64)];
    }
    __syncthreads();

    int n = chunk * 256 + tid;
    const int4* c = conn_state + n * 4;
    int4 c0 = __ldg(c + 0), c1 = __ldg(c + 1), c2 = __ldg(c + 2), c3 = __ldg(c + 3);
    unsigned addr = gather16(sw, c0, c1, c2, c3);
    float v = __ldg(mem_state + (size_t)n * TBL + addr);
    unsigned word = __ballot_sync(0xFFFFFFFFu, v > 0.5f);
    if (lane == 0) g_state_words[wr * BATCH * 32 + b * 32 + (n >> 5)] = word;
}

// ---- Output layer: grid 512 = 256 batches x 2 chunks of 256 neurons ----
__global__ __launch_bounds__(THREADS)
void k_out(const int4* __restrict__ conn_out,
           const float* __restrict__ mem_out,
           int rd, float* __restrict__ out) {
    __shared__ unsigned sw[96];

    const int b = blockIdx.x >> 1;
    const int chunk = blockIdx.x & 1;
    const int tid = threadIdx.x;

    if (tid < 64) {
        sw[tid] = g_in_words[b * 64 + tid];
    } else if (tid < 96) {
        sw[tid] = g_state_words[rd * BATCH * 32 + b * 32 + (tid - 64)];
    }
    __syncthreads();

    int n = chunk * 256 + tid;
    const int4* c = conn_out + n * 4;
    int4 c0 = __ldg(c + 0), c1 = __ldg(c + 1), c2 = __ldg(c + 2), c3 = __ldg(c + 3);
    unsigned addr = gather16(sw, c0, c1, c2, c3);
    out[b * N_OUT + n] = __ldg(mem_out + (size_t)n * TBL + addr);
}

extern "C" void kernel_launch(void* const* d_in, const int* in_sizes, int n_in,
                              void* d_out, int out_size) {
    const int* x            = (const int*)d_in[0];
    const int4* conn_in     = (const int4*)d_in[1];
    const int4* conn_state  = (const int4*)d_in[2];
    const int4* conn_out    = (const int4*)d_in[3];
    const float* mem_in     = (const float*)d_in[4];
    const float* mem_state  = (const float*)d_in[5];
    const float* mem_out    = (const float*)d_in[6];
    float* out = (float*)d_out;

    k_in<<<1024, THREADS>>>(x, conn_in, mem_in);
    // iter 0: state=0 -> write buf 0; then ping-pong; final state in buf 1.
    k_state<<<1024, THREADS>>>(conn_state, mem_state, 1, 0, 0);
    k_state<<<1024, THREADS>>>(conn_state, mem_state, 0, 0, 1);
    k_state<<<1024, THREADS>>>(conn_state, mem_state, 0, 1, 0);
    k_state<<<1024, THREADS>>>(conn_state, mem_state, 0, 0, 1);
    k_out<<<512, THREADS>>>(conn_out, mem_out, 1, out);
}

// round 3
// speedup vs baseline: 1.2031x; 1.2031x over previous
#include <cuda_runtime.h>
#include <cuda_bf16.h>

// RAM multi-step transformer — monolithic kernel, one CTA (1024 threads) per
// batch element. All bit state bit-packed in shared memory (96 words).
// Recurrence synced with __syncthreads; only the last iteration's output
// lookup survives (reference overwrites out_vals each iter).
//
// x:          (256, 1024) int32 bits
// conn_in:    (2048, 16)  int32 idx into [0,1024)
// conn_state: (1024, 16)  int32 idx into [0,3072)
// conn_out:   (512, 16)   int32 idx into [0,3072)
// mem_in: (2048,65536) f32 | mem_state: (1024,65536) f32 | mem_out: (512,65536) f32
// out:        (256, 512) f32

#define BATCH 256
#define IN_BITS 1024
#define N_IN 2048
#define N_ST 1024
#define N_OUT 512
#define TBL 65536
#define MAX_ITERS 4
#define THREADS 1024

// 16-bit address from packed bit-words in shared memory.
__device__ __forceinline__ unsigned gather16(const unsigned* __restrict__ sw,
                                             int4 c0, int4 c1, int4 c2, int4 c3) {
    unsigned a = 0;
    a |= ((sw[c0.x >> 5] >> (c0.x & 31)) & 1u) << 0;
    a |= ((sw[c0.y >> 5] >> (c0.y & 31)) & 1u) << 1;
    a |= ((sw[c0.z >> 5] >> (c0.z & 31)) & 1u) << 2;
    a |= ((sw[c0.w >> 5] >> (c0.w & 31)) & 1u) << 3;
    a |= ((sw[c1.x >> 5] >> (c1.x & 31)) & 1u) << 4;
    a |= ((sw[c1.y >> 5] >> (c1.y & 31)) & 1u) << 5;
    a |= ((sw[c1.z >> 5] >> (c1.z & 31)) & 1u) << 6;
    a |= ((sw[c1.w >> 5] >> (c1.w & 31)) & 1u) << 7;
    a |= ((sw[c2.x >> 5] >> (c2.x & 31)) & 1u) << 8;
    a |= ((sw[c2.y >> 5] >> (c2.y & 31)) & 1u) << 9;
    a |= ((sw[c2.z >> 5] >> (c2.z & 31)) & 1u) << 10;
    a |= ((sw[c2.w >> 5] >> (c2.w & 31)) & 1u) << 11;
    a |= ((sw[c3.x >> 5] >> (c3.x & 31)) & 1u) << 12;
    a |= ((sw[c3.y >> 5] >> (c3.y & 31)) & 1u) << 13;
    a |= ((sw[c3.z >> 5] >> (c3.z & 31)) & 1u) << 14;
    a |= ((sw[c3.w >> 5] >> (c3.w & 31)) & 1u) << 15;
    return a;
}

__global__ __launch_bounds__(THREADS, 1)
void ram_multistep_kernel(
    const int* __restrict__ x,
    const int4* __restrict__ conn_in,
    const int4* __restrict__ conn_state,
    const int4* __restrict__ conn_out,
    const float* __restrict__ mem_in,
    const float* __restrict__ mem_state,
    const float* __restrict__ mem_out,
    float* __restrict__ out)
{
    __shared__ unsigned sx[32];      // 1024 input bits, packed (1 word/bank -> conflict-free)
    __shared__ unsigned sbits[96];   // [0,64) in-bits (2048), [64,96) state bits (1024)

    const int b = blockIdx.x;
    const int tid = threadIdx.x;
    const int lane = tid & 31;
    const int warp = tid >> 5;       // 0..31

    // ---- Pack x bits: 1 int per thread, ballot per warp -> 32 words ----
    {
        int bit = __ldg(x + b * IN_BITS + tid);
        unsigned w = __ballot_sync(0xFFFFFFFFu, bit != 0);
        if (lane == 0) sx[warp] = w;
        // zero state words
        if (tid >= 64 && tid < 96) sbits[tid] = 0u;
    }
    __syncthreads();

    // ---- Input layer: 2048 neurons, 2 per thread, front-batched ----
    {
        const int n0 = tid;           // 0..1023
        const int n1 = tid + 1024;    // 1024..2047
        const int4* ca = conn_in + n0 * 4;
        const int4* cb = conn_in + n1 * 4;
        int4 a0 = __ldg(ca + 0), a1 = __ldg(ca + 1), a2 = __ldg(ca + 2), a3 = __ldg(ca + 3);
        int4 b0 = __ldg(cb + 0), b1 = __ldg(cb + 1), b2 = __ldg(cb + 2), b3 = __ldg(cb + 3);
        unsigned adr0 = gather16(sx, a0, a1, a2, a3);
        unsigned adr1 = gather16(sx, b0, b1, b2, b3);
        float v0 = __ldg(mem_in + (size_t)n0 * TBL + adr0);
        float v1 = __ldg(mem_in + (size_t)n1 * TBL + adr1);
        unsigned w0 = __ballot_sync(0xFFFFFFFFu, v0 > 0.5f);
        unsigned w1 = __ballot_sync(0xFFFFFFFFu, v1 > 0.5f);
        if (lane == 0) { sbits[n0 >> 5] = w0; sbits[n1 >> 5] = w1; }
    }
    __syncthreads();

    // ---- Recurrent state iterations: 1024 neurons, 1 per thread ----
    {
        const int n = tid;
        const int4* c = conn_state + n * 4;
        int4 c0 = __ldg(c + 0), c1 = __ldg(c + 1), c2 = __ldg(c + 2), c3 = __ldg(c + 3);
        for (int it = 0; it < MAX_ITERS; it++) {
            unsigned addr = gather16(sbits, c0, c1, c2, c3);
            float v = __ldg(mem_state + (size_t)n * TBL + addr);
            unsigned w = __ballot_sync(0xFFFFFFFFu, v > 0.5f);
            __syncthreads();                       // everyone done reading sbits
            if (lane == 0) sbits[64 + (n >> 5)] = w;
            __syncthreads();                       // new state visible
        }
    }

    // ---- Output layer: 512 neurons, threads 0..511 ----
    if (tid < N_OUT) {
        const int n = tid;
        const int4* c = conn_out + n * 4;
        int4 c0 = __ldg(c + 0), c1 = __ldg(c + 1), c2 = __ldg(c + 2), c3 = __ldg(c + 3);
        unsigned addr = gather16(sbits, c0, c1, c2, c3);
        out[b * N_OUT + n] = __ldg(mem_out + (size_t)n * TBL + addr);
    }
}

extern "C" void kernel_launch(void* const* d_in, const int* in_sizes, int n_in,
                              void* d_out, int out_size) {
    const int* x            = (const int*)d_in[0];
    const int4* conn_in     = (const int4*)d_in[1];
    const int4* conn_state  = (const int4*)d_in[2];
    const int4* conn_out    = (const int4*)d_in[3];
    const float* mem_in     = (const float*)d_in[4];
    const float* mem_state  = (const float*)d_in[5];
    const float* mem_out    = (const float*)d_in[6];
    float* out = (float*)d_out;

    ram_multistep_kernel<<<BATCH, THREADS>>>(x, conn_in, conn_state, conn_out,
                                             mem_in, mem_state, mem_out, out);
}

// round 4
// speedup vs baseline: 1.5684x; 1.3037x over previous
#include <cuda_runtime.h>
#include <cuda_bf16.h>

// RAM multi-step transformer — single kernel, one CTA (256 threads) per batch
// element (the round-1 shape that saturated DRAM), with:
//  * bit-packed shared gather state (96 words) instead of 3072 bytes
//  * front-batched multi-lookup per thread (8 in / 4 state / 2 out)
//  * __ldcs (ld.global.cs, streaming) for all table reads to minimize
//    per-miss fetch granularity and avoid L2 pollution by dead table lines.
//
// x: (256,1024) i32 | conn_in: (2048,16) | conn_state: (1024,16) | conn_out: (512,16)
// mem_in: (2048,65536) f32 | mem_state: (1024,65536) f32 | mem_out: (512,65536) f32
// out: (256,512) f32

#define BATCH 256
#define IN_BITS 1024
#define N_IN 2048
#define N_ST 1024
#define N_OUT 512
#define TBL 65536
#define MAX_ITERS 4
#define THREADS 256

// 16-bit address from packed bit-words in shared memory.
__device__ __forceinline__ unsigned gather16(const unsigned* __restrict__ sw,
                                             int4 c0, int4 c1, int4 c2, int4 c3) {
    unsigned a = 0;
    a |= ((sw[c0.x >> 5] >> (c0.x & 31)) & 1u) << 0;
    a |= ((sw[c0.y >> 5] >> (c0.y & 31)) & 1u) << 1;
    a |= ((sw[c0.z >> 5] >> (c0.z & 31)) & 1u) << 2;
    a |= ((sw[c0.w >> 5] >> (c0.w & 31)) & 1u) << 3;
    a |= ((sw[c1.x >> 5] >> (c1.x & 31)) & 1u) << 4;
    a |= ((sw[c1.y >> 5] >> (c1.y & 31)) & 1u) << 5;
    a |= ((sw[c1.z >> 5] >> (c1.z & 31)) & 1u) << 6;
    a |= ((sw[c1.w >> 5] >> (c1.w & 31)) & 1u) << 7;
    a |= ((sw[c2.x >> 5] >> (c2.x & 31)) & 1u) << 8;
    a |= ((sw[c2.y >> 5] >> (c2.y & 31)) & 1u) << 9;
    a |= ((sw[c2.z >> 5] >> (c2.z & 31)) & 1u) << 10;
    a |= ((sw[c2.w >> 5] >> (c2.w & 31)) & 1u) << 11;
    a |= ((sw[c3.x >> 5] >> (c3.x & 31)) & 1u) << 12;
    a |= ((sw[c3.y >> 5] >> (c3.y & 31)) & 1u) << 13;
    a |= ((sw[c3.z >> 5] >> (c3.z & 31)) & 1u) << 14;
    a |= ((sw[c3.w >> 5] >> (c3.w & 31)) & 1u) << 15;
    return a;
}

__global__ __launch_bounds__(THREADS, 2)
void ram_multistep_kernel(
    const int* __restrict__ x,
    const int4* __restrict__ conn_in,
    const int4* __restrict__ conn_state,
    const int4* __restrict__ conn_out,
    const float* __restrict__ mem_in,
    const float* __restrict__ mem_state,
    const float* __restrict__ mem_out,
    float* __restrict__ out)
{
    __shared__ unsigned sx[32];      // 1024 input bits packed
    __shared__ unsigned sbits[96];   // [0,64) in-bits, [64,96) state bits

    const int b = blockIdx.x;
    const int tid = threadIdx.x;
    const int lane = tid & 31;
    const int warp = tid >> 5;       // 0..7

    // ---- Pack x bits (coalesced, ballot) ----
    #pragma unroll
    for (int r = 0; r < 4; r++) {
        int bit = __ldg(x + b * IN_BITS + r * 256 + tid);
        unsigned w = __ballot_sync(0xFFFFFFFFu, bit != 0);
        if (lane == 0) sx[r * 8 + warp] = w;
    }
    if (tid < 32) sbits[64 + tid] = 0u;   // initial state = 0
    __syncthreads();

    // ---- Input layer: 2048 neurons, 8 per thread, addresses batched then loads batched ----
    {
        unsigned addr[8];
        #pragma unroll
        for (int r = 0; r < 8; r++) {
            int n = r * 256 + tid;
            const int4* c = conn_in + n * 4;
            int4 c0 = __ldg(c + 0), c1 = __ldg(c + 1), c2 = __ldg(c + 2), c3 = __ldg(c + 3);
            addr[r] = gather16(sx, c0, c1, c2, c3);
        }
        float v[8];
        #pragma unroll
        for (int r = 0; r < 8; r++) {
            int n = r * 256 + tid;
            v[r] = __ldcs(mem_in + (size_t)n * TBL + addr[r]);
        }
        #pragma unroll
        for (int r = 0; r < 8; r++) {
            unsigned w = __ballot_sync(0xFFFFFFFFu, v[r] > 0.5f);
            if (lane == 0) sbits[r * 8 + warp] = w;
        }
    }
    __syncthreads();

    // ---- Recurrent state iterations: 1024 neurons, 4 per thread ----
    for (int it = 0; it < MAX_ITERS; it++) {
        unsigned addr[4];
        #pragma unroll
        for (int k = 0; k < 4; k++) {
            int n = k * 256 + tid;
            const int4* c = conn_state + n * 4;
            int4 c0 = __ldg(c + 0), c1 = __ldg(c + 1), c2 = __ldg(c + 2), c3 = __ldg(c + 3);
            addr[k] = gather16(sbits, c0, c1, c2, c3);
        }
        float v[4];
        #pragma unroll
        for (int k = 0; k < 4; k++) {
            int n = k * 256 + tid;
            v[k] = __ldcs(mem_state + (size_t)n * TBL + addr[k]);
        }
        unsigned w[4];
        #pragma unroll
        for (int k = 0; k < 4; k++)
            w[k] = __ballot_sync(0xFFFFFFFFu, v[k] > 0.5f);
        __syncthreads();                 // all reads of sbits done
        if (lane == 0) {
            #pragma unroll
            for (int k = 0; k < 4; k++)
                sbits[64 + k * 8 + warp] = w[k];
        }
        __syncthreads();                 // new state visible
    }

    // ---- Output layer: 512 neurons, 2 per thread (last iteration only) ----
    {
        unsigned addr[2];
        #pragma unroll
        for (int r = 0; r < 2; r++) {
            int n = r * 256 + tid;
            const int4* c = conn_out + n * 4;
            int4 c0 = __ldg(c + 0), c1 = __ldg(c + 1), c2 = __ldg(c + 2), c3 = __ldg(c + 3);
            addr[r] = gather16(sbits, c0, c1, c2, c3);
        }
        #pragma unroll
        for (int r = 0; r < 2; r++) {
            int n = r * 256 + tid;
            out[b * N_OUT + n] = __ldcs(mem_out + (size_t)n * TBL + addr[r]);
        }
    }
}

extern "C" void kernel_launch(void* const* d_in, const int* in_sizes, int n_in,
                              void* d_out, int out_size) {
    const int* x            = (const int*)d_in[0];
    const int4* conn_in     = (const int4*)d_in[1];
    const int4* conn_state  = (const int4*)d_in[2];
    const int4* conn_out    = (const int4*)d_in[3];
    const float* mem_in     = (const float*)d_in[4];
    const float* mem_state  = (const float*)d_in[5];
    const float* mem_out    = (const float*)d_in[6];
    float* out = (float*)d_out;

    ram_multistep_kernel<<<BATCH, THREADS>>>(x, conn_in, conn_state, conn_out,
                                             mem_in, mem_state, mem_out, out);
}

// round 6
// speedup vs baseline: 1.6635x; 1.0606x over previous
#include <cuda_runtime.h>
#include <cuda_bf16.h>

// RAM multi-step transformer — single kernel, one CTA (256 threads) per batch.
//  * bit-packed shared gather state, double-buffered (1 barrier per state iter)
//  * front-batched lookups (8 in / 4 state / 2 out per thread)
//  * L2 policy via createpolicy+cache_hint: mem_in/mem_out = evict_last
//    (touched-line working set ~84MB fits L2 and repeats identically every
//    graph replay), mem_state = evict_first (streaming; exceeds L2).
//
// x: (256,1024) i32 | conn_in: (2048,16) | conn_state: (1024,16) | conn_out: (512,16)
// mem_in: (2048,65536) f32 | mem_state: (1024,65536) f32 | mem_out: (512,65536) f32
// out: (256,512) f32

#define BATCH 256
#define IN_BITS 1024
#define N_IN 2048
#define N_ST 1024
#define N_OUT 512
#define TBL 65536
#define MAX_ITERS 4
#define THREADS 256

__device__ __forceinline__ unsigned long long mk_policy_last() {
    unsigned long long pol;
    asm("createpolicy.fractional.L2::evict_last.b64 %0, 1.0;" : "=l"(pol));
    return pol;
}
__device__ __forceinline__ unsigned long long mk_policy_first() {
    unsigned long long pol;
    asm("createpolicy.fractional.L2::evict_first.b64 %0, 1.0;" : "=l"(pol));
    return pol;
}
__device__ __forceinline__ float ld_hint(const float* p, unsigned long long pol) {
    float v;
    asm("ld.global.nc.L2::cache_hint.f32 %0, [%1], %2;" : "=f"(v) : "l"(p), "l"(pol));
    return v;
}

// 16-bit address from packed bit-words in shared memory.
__device__ __forceinline__ unsigned gather16(const unsigned* __restrict__ sw,
                                             int4 c0, int4 c1, int4 c2, int4 c3) {
    unsigned a = 0;
    a |= ((sw[c0.x >> 5] >> (c0.x & 31)) & 1u) << 0;
    a |= ((sw[c0.y >> 5] >> (c0.y & 31)) & 1u) << 1;
    a |= ((sw[c0.z >> 5] >> (c0.z & 31)) & 1u) << 2;
    a |= ((sw[c0.w >> 5] >> (c0.w & 31)) & 1u) << 3;
    a |= ((sw[c1.x >> 5] >> (c1.x & 31)) & 1u) << 4;
    a |= ((sw[c1.y >> 5] >> (c1.y & 31)) & 1u) << 5;
    a |= ((sw[c1.z >> 5] >> (c1.z & 31)) & 1u) << 6;
    a |= ((sw[c1.w >> 5] >> (c1.w & 31)) & 1u) << 7;
    a |= ((sw[c2.x >> 5] >> (c2.x & 31)) & 1u) << 8;
    a |= ((sw[c2.y >> 5] >> (c2.y & 31)) & 1u) << 9;
    a |= ((sw[c2.z >> 5] >> (c2.z & 31)) & 1u) << 10;
    a |= ((sw[c2.w >> 5] >> (c2.w & 31)) & 1u) << 11;
    a |= ((sw[c3.x >> 5] >> (c3.x & 31)) & 1u) << 12;
    a |= ((sw[c3.y >> 5] >> (c3.y & 31)) & 1u) << 13;
    a |= ((sw[c3.z >> 5] >> (c3.z & 31)) & 1u) << 14;
    a |= ((sw[c3.w >> 5] >> (c3.w & 31)) & 1u) << 15;
    return a;
}

__global__ __launch_bounds__(THREADS, 2)
void ram_multistep_kernel(
    const int* __restrict__ x,
    const int4* __restrict__ conn_in,
    const int4* __restrict__ conn_state,
    const int4* __restrict__ conn_out,
    const float* __restrict__ mem_in,
    const float* __restrict__ mem_state,
    const float* __restrict__ mem_out,
    float* __restrict__ out)
{
    __shared__ unsigned sx[32];       // 1024 input bits packed
    __shared__ unsigned sbufA[96];    // [0,64) in-bits, [64,96) state bits
    __shared__ unsigned sbufB[96];    // double buffer

    const int b = blockIdx.x;
    const int tid = threadIdx.x;
    const int lane = tid & 31;
    const int warp = tid >> 5;        // 0..7

    const unsigned long long pol_last  = mk_policy_last();
    const unsigned long long pol_first = mk_policy_first();

    // ---- Pack x bits (coalesced, ballot) ----
    #pragma unroll
    for (int r = 0; r < 4; r++) {
        int bit = __ldg(x + b * IN_BITS + r * 256 + tid);
        unsigned w = __ballot_sync(0xFFFFFFFFu, bit != 0);
        if (lane == 0) sx[r * 8 + warp] = w;
    }
    if (tid < 32) sbufA[64 + tid] = 0u;    // initial state = 0 (read by iter 0)
    __syncthreads();

    // ---- Input layer: 2048 neurons, 8 per thread, addr batch then load batch ----
    {
        unsigned addr[8];
        #pragma unroll
        for (int r = 0; r < 8; r++) {
            int n = r * 256 + tid;
            const int4* c = conn_in + n * 4;
            int4 c0 = __ldg(c + 0), c1 = __ldg(c + 1), c2 = __ldg(c + 2), c3 = __ldg(c + 3);
            addr[r] = gather16(sx, c0, c1, c2, c3);
        }
        float v[8];
        #pragma unroll
        for (int r = 0; r < 8; r++) {
            int n = r * 256 + tid;
            v[r] = ld_hint(mem_in + (size_t)n * TBL + addr[r], pol_last);
        }
        #pragma unroll
        for (int r = 0; r < 8; r++) {
            unsigned w = __ballot_sync(0xFFFFFFFFu, v[r] > 0.5f);
            if (lane == 0) { sbufA[r * 8 + warp] = w; sbufB[r * 8 + warp] = w; }
        }
    }
    __syncthreads();

    // ---- Recurrent state iterations: 4 per thread, double-buffered, 1 barrier/iter ----
    unsigned* cur = sbufA;
    unsigned* nxt = sbufB;
    for (int it = 0; it < MAX_ITERS; it++) {
        unsigned addr[4];
        #pragma unroll
        for (int k = 0; k < 4; k++) {
            int n = k * 256 + tid;
            const int4* c = conn_state + n * 4;
            int4 c0 = __ldg(c + 0), c1 = __ldg(c + 1), c2 = __ldg(c + 2), c3 = __ldg(c + 3);
            addr[k] = gather16(cur, c0, c1, c2, c3);
        }
        float v[4];
        #pragma unroll
        for (int k = 0; k < 4; k++) {
            int n = k * 256 + tid;
            v[k] = ld_hint(mem_state + (size_t)n * TBL + addr[k], pol_first);
        }
        #pragma unroll
        for (int k = 0; k < 4; k++) {
            unsigned w = __ballot_sync(0xFFFFFFFFu, v[k] > 0.5f);
            if (lane == 0) nxt[64 + k * 8 + warp] = w;   // disjoint from cur: no pre-barrier
        }
        __syncthreads();                 // nxt complete & visible
        unsigned* t = cur; cur = nxt; nxt = t;
    }

    // ---- Output layer: 512 neurons, 2 per thread (final state only) ----
    {
        unsigned addr[2];
        #pragma unroll
        for (int r = 0; r < 2; r++) {
            int n = r * 256 + tid;
            const int4* c = conn_out + n * 4;
            int4 c0 = __ldg(c + 0), c1 = __ldg(c + 1), c2 = __ldg(c + 2), c3 = __ldg(c + 3);
            addr[r] = gather16(cur, c0, c1, c2, c3);
        }
        #pragma unroll
        for (int r = 0; r < 2; r++) {
            int n = r * 256 + tid;
            out[b * N_OUT + n] = ld_hint(mem_out + (size_t)n * TBL + addr[r], pol_last);
        }
    }
}

extern "C" void kernel_launch(void* const* d_in, const int* in_sizes, int n_in,
                              void* d_out, int out_size) {
    const int* x            = (const int*)d_in[0];
    const int4* conn_in     = (const int4*)d_in[1];
    const int4* conn_state  = (const int4*)d_in[2];
    const int4* conn_out    = (const int4*)d_in[3];
    const float* mem_in     = (const float*)d_in[4];
    const float* mem_state  = (const float*)d_in[5];
    const float* mem_out    = (const float*)d_in[6];
    float* out = (float*)d_out;

    ram_multistep_kernel<<<BATCH, THREADS>>>(x, conn_in, conn_state, conn_out,
                                             mem_in, mem_state, mem_out, out);
}